// round 2
// baseline (speedup 1.0000x reference)
#include <cuda_runtime.h>
#include <math.h>

// Shapes (fixed by the problem)
#define B_ 8
#define N_ 3
#define C_ 64
#define F_ 128
#define H_ 128
#define W_ 128
#define h_ 64
#define w_ 64

typedef unsigned long long u64t;

// Scratch (device globals -- no allocation allowed)
__device__ float g_A[C_ * F_];              // Wc^T * Wf  [c][f]
__device__ float g_tvec[C_];                // Wc^T * bf
__device__ float g_Qt[B_ * C_ * h_ * w_];   // qt at low res
__device__ float g_Val[B_ * C_ * h_ * w_];  // values at low res
__device__ float g_Lm[B_ * h_ * w_];        // mainstream-key logit

// ---- packed f32x2 helpers (FFMA2 path: only reachable via PTX) ----
__device__ __forceinline__ u64t pk2(float lo, float hi) {
    u64t r; asm("mov.b64 %0, {%1, %2};" : "=l"(r) : "f"(lo), "f"(hi)); return r;
}
__device__ __forceinline__ u64t bc2(float v) { return pk2(v, v); }
__device__ __forceinline__ void unpk(u64t p, float& lo, float& hi) {
    asm("mov.b64 {%0, %1}, %2;" : "=f"(lo), "=f"(hi) : "l"(p));
}
__device__ __forceinline__ void fma2(u64t& d, u64t a, u64t b) {
    asm("fma.rn.f32x2 %0, %1, %2, %0;" : "+l"(d) : "l"(a), "l"(b));
}
__device__ __forceinline__ u64t add2(u64t a, u64t b) {
    u64t r; asm("add.rn.f32x2 %0, %1, %2;" : "=l"(r) : "l"(a), "l"(b)); return r;
}
__device__ __forceinline__ u64t mul2(u64t a, u64t b) {
    u64t r; asm("mul.rn.f32x2 %0, %1, %2;" : "=l"(r) : "l"(a), "l"(b)); return r;
}

// ---------------------------------------------------------------------------
// Kernel 0: A = Wc^T Wf and tvec = Wc^T bf.  Wc staged in SMEM, 4-way ILP.
// ---------------------------------------------------------------------------
__global__ __launch_bounds__(1024) void k0_precompute(const float* __restrict__ Wc,
                                                      const float* __restrict__ Wf,
                                                      const float* __restrict__ bf) {
    __shared__ float sWc[64 * 64];
    int tid = threadIdx.x;
    for (int i = tid; i < 4096; i += 1024) sWc[i] = Wc[i];
    __syncthreads();
    int i = blockIdx.x * 1024 + tid;  // 8192 outputs over 8 blocks
    int c = i >> 7, f = i & 127;
    float s0 = 0.f, s1 = 0.f, s2 = 0.f, s3 = 0.f;
#pragma unroll
    for (int d = 0; d < 64; d += 4) {
        s0 = fmaf(sWc[d * 64 + c],       Wf[d * 128 + f],       s0);
        s1 = fmaf(sWc[(d + 1) * 64 + c], Wf[(d + 1) * 128 + f], s1);
        s2 = fmaf(sWc[(d + 2) * 64 + c], Wf[(d + 2) * 128 + f], s2);
        s3 = fmaf(sWc[(d + 3) * 64 + c], Wf[(d + 3) * 128 + f], s3);
    }
    g_A[i] = (s0 + s1) + (s2 + s3);
    if (blockIdx.x == 0 && tid < 64) {
        float t = 0.f;
        for (int d = 0; d < 64; d++) t += sWc[d * 64 + tid] * bf[d];
        g_tvec[tid] = t;
    }
}

// ---------------------------------------------------------------------------
// Kernel 1 (f32x2): per low-res pixel
//   qt[c] = sum_f A[c,f] m[f] + tvec[c]
//   key[c]= sum_f Wk[c,f] m[f] + bk[c]   (only for Lm = sum_c key*qt)
//   val[c]= 3x3 conv(m,Vw)[c] + Vb[c]
// Block = 16x8 pixel tile of one batch, 256 threads:
//   cg = tid&31  -> channels {2cg, 2cg+1}
//   pg = tid>>5  -> output rows {2pg, 2pg+1}, packed in f32x2 lanes
// Window staged in SMEM as row-PAIRS (float2), so every stencil operand pair
// is an aligned LDS.64. Weights staged scalar, broadcast-packed via mov.b64.
// ---------------------------------------------------------------------------
#define SWIN 0        // float2[8 fc][17 rowpairs][10 cols] = 2720 floats
#define SWA  2720     // [8 fc][64 c] = 512
#define SWK  3232     // 512
#define SWV  3744     // [8 fc][64 c][pitch 11] = 5632
#define STOT 9376     // 37.5 KB; epilogue stage reuses [64][129] = 8256

__global__ __launch_bounds__(256, 1) void k1_lowres(
    const float* __restrict__ ms,   // [B,128,64,64]
    const float* __restrict__ Wk,   // [64,128]
    const float* __restrict__ bk,   // [64]
    const float* __restrict__ Vw,   // [64,128,3,3]
    const float* __restrict__ Vb)   // [64]
{
    __shared__ __align__(16) float sm[STOT];

    const int tid = threadIdx.x;
    const int b = blockIdx.z;
    const int gx0 = blockIdx.x * 8, gy0 = blockIdx.y * 16;
    const int cg = tid & 31, pg = tid >> 5;
    const int c0 = 2 * cg;

    u64t vq0[8], vq1[8], vk0[8], vk1[8], vv0[8], vv1[8];
#pragma unroll
    for (int x = 0; x < 8; x++) {
        vq0[x] = vq1[x] = vk0[x] = vk1[x] = vv0[x] = vv1[x] = 0ull;
    }

    for (int chunk = 0; chunk < 16; chunk++) {
        const int f0 = chunk * 8;
        __syncthreads();
        // ---- stage window row-pairs (zero-padded SAME halo) ----
        for (int i = tid; i < 1360; i += 256) {
            int fc = i / 170;
            int rem = i - fc * 170;
            int j = rem / 10, col = rem - j * 10;
            int gy = gy0 + j - 1, gx = gx0 + col - 1;
            float lo = 0.f, hi = 0.f;
            if (gx >= 0 && gx < w_) {
                const float* base = ms + ((size_t)(b * F_ + f0 + fc) * h_) * w_ + gx;
                if (gy >= 0 && gy < h_) lo = base[gy * w_];
                if (gy + 1 < h_) hi = base[(gy + 1) * w_];
            }
            ((float2*)sm)[i] = make_float2(lo, hi);
        }
        // ---- stage weights (scalar) ----
        for (int i = tid; i < 512; i += 256) {
            int cc = i >> 3, fc = i & 7;
            sm[SWA + fc * 64 + cc] = g_A[cc * F_ + f0 + fc];
            sm[SWK + fc * 64 + cc] = Wk[cc * F_ + f0 + fc];
        }
        for (int i = tid; i < 4608; i += 256) {
            int cc = i / 72;
            int r = i - cc * 72;
            int fc = r / 9, j = r - fc * 9;
            sm[SWV + (fc * 64 + cc) * 11 + j] = Vw[(cc * F_ + f0 + fc) * 9 + j];
        }
        __syncthreads();

#pragma unroll 1
        for (int fc = 0; fc < 8; fc++) {
            float2 wa = *(const float2*)&sm[SWA + fc * 64 + c0];
            float2 wkw = *(const float2*)&sm[SWK + fc * 64 + c0];
            u64t wap0 = bc2(wa.x), wap1 = bc2(wa.y);
            u64t wkp0 = bc2(wkw.x), wkp1 = bc2(wkw.y);
            u64t vwp0[9], vwp1[9];
#pragma unroll
            for (int j = 0; j < 9; j++) {
                vwp0[j] = bc2(sm[SWV + (fc * 64 + c0) * 11 + j]);
                vwp1[j] = bc2(sm[SWV + (fc * 64 + c0 + 1) * 11 + j]);
            }
            const u64t* win = (const u64t*)sm + (fc * 17 + 2 * pg) * 10;
#pragma unroll
            for (int u = 0; u < 3; u++) {
                u64t w[10];
#pragma unroll
                for (int t = 0; t < 10; t++) w[t] = win[u * 10 + t];
#pragma unroll
                for (int x = 0; x < 8; x++) {
                    fma2(vv0[x], vwp0[3 * u + 0], w[x]);
                    fma2(vv0[x], vwp0[3 * u + 1], w[x + 1]);
                    fma2(vv0[x], vwp0[3 * u + 2], w[x + 2]);
                    fma2(vv1[x], vwp1[3 * u + 0], w[x]);
                    fma2(vv1[x], vwp1[3 * u + 1], w[x + 1]);
                    fma2(vv1[x], vwp1[3 * u + 2], w[x + 2]);
                }
                if (u == 1) {
#pragma unroll
                    for (int x = 0; x < 8; x++) {
                        fma2(vq0[x], wap0, w[x + 1]);
                        fma2(vq1[x], wap1, w[x + 1]);
                        fma2(vk0[x], wkp0, w[x + 1]);
                        fma2(vk1[x], wkp1, w[x + 1]);
                    }
                }
            }
        }
    }

    // ---- epilogue ----
    u64t tqp0 = bc2(g_tvec[c0]), tqp1 = bc2(g_tvec[c0 + 1]);
    u64t kbp0 = bc2(bk[c0]), kbp1 = bc2(bk[c0 + 1]);
    u64t vbp0 = bc2(Vb[c0]), vbp1 = bc2(Vb[c0 + 1]);

    u64t qf0[8], qf1[8], lm[8];
#pragma unroll
    for (int x = 0; x < 8; x++) {
        qf0[x] = add2(vq0[x], tqp0);
        qf1[x] = add2(vq1[x], tqp1);
        u64t kf0 = add2(vk0[x], kbp0);
        u64t kf1 = add2(vk1[x], kbp1);
        lm[x] = add2(mul2(kf0, qf0[x]), mul2(kf1, qf1[x]));
    }
    // warp reduce over cg (lanes) -> sum over all 64 channels
#pragma unroll
    for (int off = 16; off; off >>= 1) {
#pragma unroll
        for (int x = 0; x < 8; x++)
            lm[x] = add2(lm[x], __shfl_down_sync(0xffffffffu, lm[x], off));
    }
    if ((tid & 31) == 0) {
#pragma unroll
        for (int x = 0; x < 8; x++) {
            float lo, hi; unpk(lm[x], lo, hi);
            g_Lm[(b * h_ + gy0 + 2 * pg) * w_ + gx0 + x] = lo;
            g_Lm[(b * h_ + gy0 + 2 * pg + 1) * w_ + gx0 + x] = hi;
        }
    }

    // stage q (transpose to [c][row][col]) then coalesced store
    __syncthreads();
#pragma unroll
    for (int x = 0; x < 8; x++) {
        float lo, hi;
        unpk(qf0[x], lo, hi);
        sm[c0 * 129 + 16 * pg + x] = lo;
        sm[c0 * 129 + 16 * pg + 8 + x] = hi;
        unpk(qf1[x], lo, hi);
        sm[(c0 + 1) * 129 + 16 * pg + x] = lo;
        sm[(c0 + 1) * 129 + 16 * pg + 8 + x] = hi;
    }
    __syncthreads();
#pragma unroll
    for (int j = 0; j < 32; j++) {
        int i = j * 256 + tid;
        int c = i >> 7, px = i & 127;
        g_Qt[((b * C_ + c) * h_ + gy0 + (px >> 3)) * w_ + gx0 + (px & 7)] =
            sm[c * 129 + px];
    }
    __syncthreads();
#pragma unroll
    for (int x = 0; x < 8; x++) {
        float lo, hi;
        unpk(add2(vv0[x], vbp0), lo, hi);
        sm[c0 * 129 + 16 * pg + x] = lo;
        sm[c0 * 129 + 16 * pg + 8 + x] = hi;
        unpk(add2(vv1[x], vbp1), lo, hi);
        sm[(c0 + 1) * 129 + 16 * pg + x] = lo;
        sm[(c0 + 1) * 129 + 16 * pg + 8 + x] = hi;
    }
    __syncthreads();
#pragma unroll
    for (int j = 0; j < 32; j++) {
        int i = j * 256 + tid;
        int c = i >> 7, px = i & 127;
        g_Val[((b * C_ + c) * h_ + gy0 + (px >> 3)) * w_ + gx0 + (px & 7)] =
            sm[c * 129 + px];
    }
}

// ---------------------------------------------------------------------------
// Kernel 2: high-res attention. One thread per output pixel.
// ---------------------------------------------------------------------------
__global__ __launch_bounds__(256) void k2_highres(const float* __restrict__ ctx,
                                                  float* __restrict__ out) {
    int idx = blockIdx.x * 256 + threadIdx.x;
    int b = idx >> 14;
    int hw = idx & 16383;
    int h = hw >> 7, w = hw & 127;
    int y = h >> 1, x = w >> 1;

    const float* qt = g_Qt + ((b * C_) * h_ + y) * w_ + x;
    const float* cp = ctx + (size_t)b * N_ * C_ * (H_ * W_) + hw;

    float l0 = 0.f, l1 = 0.f, l2 = 0.f;
#pragma unroll 4
    for (int c = 0; c < C_; c++) {
        float q = qt[c * 4096];
        l0 = fmaf(cp[c * 16384], q, l0);
        l1 = fmaf(cp[(64 + c) * 16384], q, l1);
        l2 = fmaf(cp[(128 + c) * 16384], q, l2);
    }
    float l3 = g_Lm[(b * h_ + y) * w_ + x];

    float mx = fmaxf(fmaxf(l0, l1), fmaxf(l2, l3));
    float e0 = __expf(l0 - mx), e1 = __expf(l1 - mx);
    float e2 = __expf(l2 - mx), e3 = __expf(l3 - mx);
    float inv = 1.f / (e0 + e1 + e2 + e3);
    e0 *= inv; e1 *= inv; e2 *= inv; e3 *= inv;

    const float* vp = g_Val + ((b * C_) * h_ + y) * w_ + x;
    float* op = out + (size_t)b * C_ * (H_ * W_) + hw;
#pragma unroll 4
    for (int c = 0; c < C_; c++) {
        float o = e3 * vp[c * 4096];
        o = fmaf(e0, cp[c * 16384], o);
        o = fmaf(e1, cp[(64 + c) * 16384], o);
        o = fmaf(e2, cp[(128 + c) * 16384], o);
        op[c * 16384] = o;
    }
}

// ---------------------------------------------------------------------------
extern "C" void kernel_launch(void* const* d_in, const int* in_sizes, int n_in,
                              void* d_out, int out_size) {
    (void)in_sizes; (void)n_in; (void)out_size;
    const float* contexts = (const float*)d_in[0];
    const float* mainstream = (const float*)d_in[1];
    const float* Wc = (const float*)d_in[2];
    // d_in[3] = bc : cancels in softmax, unused
    const float* Wf = (const float*)d_in[4];
    const float* bf = (const float*)d_in[5];
    const float* Wk = (const float*)d_in[6];
    const float* bk = (const float*)d_in[7];
    const float* Vw = (const float*)d_in[8];
    const float* Vb = (const float*)d_in[9];
    float* out = (float*)d_out;

    k0_precompute<<<8, 1024>>>(Wc, Wf, bf);
    dim3 g1(8, 4, 8);  // x tiles (8 cols), y tiles (16 rows), batch
    k1_lowres<<<g1, 256>>>(mainstream, Wk, bk, Vw, Vb);
    k2_highres<<<512, 256>>>(contexts, out);
}

// round 3
// speedup vs baseline: 1.1085x; 1.1085x over previous
#include <cuda_runtime.h>
#include <math.h>

#define B_ 8
#define N_ 3
#define C_ 64
#define F_ 128
#define H_ 128
#define W_ 128
#define h_ 64
#define w_ 64

typedef unsigned long long u64t;

// Scratch (device globals -- no allocation allowed)
__device__ float g_A[C_ * F_];              // Wc^T * Wf  [c][f]
__device__ float g_tvec[C_];                // Wc^T * bf
__device__ float g_Qt[B_ * C_ * h_ * w_];   // qt at low res
__device__ float g_Val[B_ * C_ * h_ * w_];  // values at low res
__device__ float g_Lm[B_ * h_ * w_];        // mainstream-key logit

// ---- packed f32x2 helpers ----
__device__ __forceinline__ u64t pk2(float lo, float hi) {
    u64t r; asm("mov.b64 %0, {%1, %2};" : "=l"(r) : "f"(lo), "f"(hi)); return r;
}
__device__ __forceinline__ u64t bc2(float v) { return pk2(v, v); }
__device__ __forceinline__ void unpk(u64t p, float& lo, float& hi) {
    asm("mov.b64 {%0, %1}, %2;" : "=f"(lo), "=f"(hi) : "l"(p));
}
__device__ __forceinline__ void fma2(u64t& d, u64t a, u64t b) {
    asm("fma.rn.f32x2 %0, %1, %2, %0;" : "+l"(d) : "l"(a), "l"(b));
}
__device__ __forceinline__ u64t add2(u64t a, u64t b) {
    u64t r; asm("add.rn.f32x2 %0, %1, %2;" : "=l"(r) : "l"(a), "l"(b)); return r;
}
__device__ __forceinline__ u64t mul2(u64t a, u64t b) {
    u64t r; asm("mul.rn.f32x2 %0, %1, %2;" : "=l"(r) : "l"(a), "l"(b)); return r;
}

// ---------------------------------------------------------------------------
// Kernel 0: A = Wc^T Wf, tvec = Wc^T bf
// ---------------------------------------------------------------------------
__global__ __launch_bounds__(256) void k0_precompute(const float* __restrict__ Wc,
                                                     const float* __restrict__ Wf,
                                                     const float* __restrict__ bf) {
    int i = blockIdx.x * blockDim.x + threadIdx.x;  // 8192 threads
    int c = i >> 7, f = i & 127;
    float s0 = 0.f, s1 = 0.f, s2 = 0.f, s3 = 0.f;
#pragma unroll
    for (int d = 0; d < 64; d += 4) {
        s0 = fmaf(Wc[d * 64 + c],       Wf[d * 128 + f],       s0);
        s1 = fmaf(Wc[(d + 1) * 64 + c], Wf[(d + 1) * 128 + f], s1);
        s2 = fmaf(Wc[(d + 2) * 64 + c], Wf[(d + 2) * 128 + f], s2);
        s3 = fmaf(Wc[(d + 3) * 64 + c], Wf[(d + 3) * 128 + f], s3);
    }
    g_A[i] = (s0 + s1) + (s2 + s3);
    if (i < 64) {
        float t = 0.f;
        for (int d = 0; d < 64; d++) t += Wc[d * 64 + i] * bf[d];
        g_tvec[i] = t;
    }
}

// ---------------------------------------------------------------------------
// Kernel 1 (f32x2, 512 threads): per low-res pixel
//   qt[c] = sum_f A[c,f] m[f] + tvec[c]
//   key[c]= sum_f Wk[c,f] m[f] + bk[c]   (only for Lm = sum_c key*qt)
//   val[c]= 3x3 conv(m,Vw)[c] + Vb[c]
// Block = 16x8 pixel tile of one batch, 512 threads:
//   c  = tid&63   -> one channel
//   pg = tid>>6   -> output row-pair {2pg, 2pg+1}, packed in f32x2 lanes
// Window staged in SMEM as row-PAIRS (float2) so every stencil operand pair is
// an aligned broadcast LDS.64. Weight scalars broadcast-packed via mov.b64.
// ---------------------------------------------------------------------------
#define SWIN 0        // float2[8 fc][17 pairs][10 cols] = 2720 floats
#define SWA  2720     // [8 fc][64 c] = 512
#define SWK  3232     // 512
#define SWV  3744     // [8 fc][64 c][9] = 4608
#define SRED 8352     // u64[16 warps][8 x] = 256 floats
#define STOT 8608     // 34.4 KB; epilogue stage reuses [64][129]=8256 at 0

__global__ __launch_bounds__(512, 1) void k1_lowres(
    const float* __restrict__ ms,   // [B,128,64,64]
    const float* __restrict__ Wk,   // [64,128]
    const float* __restrict__ bk,   // [64]
    const float* __restrict__ Vw,   // [64,128,3,3]
    const float* __restrict__ Vb)   // [64]
{
    __shared__ __align__(16) float sm[STOT];

    const int tid = threadIdx.x;
    const int b = blockIdx.z;
    const int gx0 = blockIdx.x * 8, gy0 = blockIdx.y * 16;
    const int c = tid & 63, pg = tid >> 6;

    u64t vq[8], vk[8], vv[8];
#pragma unroll
    for (int x = 0; x < 8; x++) { vq[x] = vk[x] = vv[x] = 0ull; }

    for (int chunk = 0; chunk < 16; chunk++) {
        const int f0 = chunk * 8;
        __syncthreads();
        // ---- stage window row-pairs (zero-padded SAME halo) ----
        for (int i = tid; i < 1360; i += 512) {
            int fc = i / 170;
            int rem = i - fc * 170;
            int j = rem / 10, col = rem - j * 10;
            int gy = gy0 + j - 1, gx = gx0 + col - 1;
            float lo = 0.f, hi = 0.f;
            if (gx >= 0 && gx < w_) {
                const float* base = ms + ((size_t)(b * F_ + f0 + fc) * h_) * w_ + gx;
                if (gy >= 0 && gy < h_) lo = base[gy * w_];
                if (gy + 1 < h_) hi = base[(gy + 1) * w_];
            }
            ((float2*)sm)[i] = make_float2(lo, hi);
        }
        // ---- stage weights ----
        {
            int cc = tid >> 3, fc = tid & 7;
            sm[SWA + fc * 64 + cc] = g_A[cc * F_ + f0 + fc];
            sm[SWK + fc * 64 + cc] = Wk[cc * F_ + f0 + fc];
        }
        for (int i = tid; i < 4608; i += 512) {
            int cc = i / 72;
            int r = i - cc * 72;
            int fc = r / 9, j = r - fc * 9;
            sm[SWV + (fc * 64 + cc) * 9 + j] = Vw[(cc * F_ + f0 + fc) * 9 + j];
        }
        __syncthreads();

#pragma unroll 1
        for (int fc = 0; fc < 8; fc++) {
            u64t wap = bc2(sm[SWA + fc * 64 + c]);
            u64t wkp = bc2(sm[SWK + fc * 64 + c]);
            u64t vwp[9];
#pragma unroll
            for (int j = 0; j < 9; j++)
                vwp[j] = bc2(sm[SWV + (fc * 64 + c) * 9 + j]);
            const u64t* win = (const u64t*)sm + (fc * 17 + 2 * pg) * 10;
#pragma unroll
            for (int u = 0; u < 3; u++) {
                u64t w[10];
#pragma unroll
                for (int t = 0; t < 10; t++) w[t] = win[u * 10 + t];
#pragma unroll
                for (int x = 0; x < 8; x++) {
                    fma2(vv[x], vwp[3 * u + 0], w[x]);
                    fma2(vv[x], vwp[3 * u + 1], w[x + 1]);
                    fma2(vv[x], vwp[3 * u + 2], w[x + 2]);
                }
                if (u == 1) {
#pragma unroll
                    for (int x = 0; x < 8; x++) {
                        fma2(vq[x], wap, w[x + 1]);
                        fma2(vk[x], wkp, w[x + 1]);
                    }
                }
            }
        }
    }

    // ---- epilogue ----
    u64t tqp = bc2(g_tvec[c]);
    u64t kbp = bc2(bk[c]);
    u64t vbp = bc2(Vb[c]);

    u64t qf[8], lm[8];
#pragma unroll
    for (int x = 0; x < 8; x++) {
        qf[x] = add2(vq[x], tqp);
        lm[x] = mul2(add2(vk[x], kbp), qf[x]);
    }
    // warp shuffle-reduce over 32 channels (warp has fixed pg)
#pragma unroll
    for (int off = 16; off; off >>= 1) {
#pragma unroll
        for (int x = 0; x < 8; x++)
            lm[x] = add2(lm[x], __shfl_down_sync(0xffffffffu, lm[x], off));
    }
    __syncthreads();  // compute done; smem reusable
    const int warp = tid >> 5;
    if ((tid & 31) == 0) {
        u64t* red = (u64t*)sm + SRED / 2;
#pragma unroll
        for (int x = 0; x < 8; x++) red[warp * 8 + x] = lm[x];
    }
    // stage q transposed to [c][16 rows][8 cols] (pitch 129 kills conflicts)
#pragma unroll
    for (int x = 0; x < 8; x++) {
        float lo, hi; unpk(qf[x], lo, hi);
        sm[c * 129 + (2 * pg) * 8 + x] = lo;
        sm[c * 129 + (2 * pg + 1) * 8 + x] = hi;
    }
    __syncthreads();
    if (tid < 64) {  // combine the two warps per pg, write Lm
        int pg2 = tid >> 3, x = tid & 7;
        const u64t* red = (const u64t*)sm + SRED / 2;
        u64t L = add2(red[(2 * pg2) * 8 + x], red[(2 * pg2 + 1) * 8 + x]);
        float lo, hi; unpk(L, lo, hi);
        g_Lm[(b * h_ + gy0 + 2 * pg2) * w_ + gx0 + x] = lo;
        g_Lm[(b * h_ + gy0 + 2 * pg2 + 1) * w_ + gx0 + x] = hi;
    }
#pragma unroll
    for (int j = 0; j < 16; j++) {
        int i = j * 512 + tid;
        int cc = i >> 7, p = i & 127;
        g_Qt[((b * C_ + cc) * h_ + gy0 + (p >> 3)) * w_ + gx0 + (p & 7)] =
            sm[cc * 129 + p];
    }
    __syncthreads();
#pragma unroll
    for (int x = 0; x < 8; x++) {
        float lo, hi; unpk(add2(vv[x], vbp), lo, hi);
        sm[c * 129 + (2 * pg) * 8 + x] = lo;
        sm[c * 129 + (2 * pg + 1) * 8 + x] = hi;
    }
    __syncthreads();
#pragma unroll
    for (int j = 0; j < 16; j++) {
        int i = j * 512 + tid;
        int cc = i >> 7, p = i & 127;
        g_Val[((b * C_ + cc) * h_ + gy0 + (p >> 3)) * w_ + gx0 + (p & 7)] =
            sm[cc * 129 + p];
    }
}

// ---------------------------------------------------------------------------
// Kernel 2: high-res attention. One thread per 2 adjacent output pixels
// (same low-res source pixel) -> float2 ctx loads, amortized qt/Lm/Val.
// ---------------------------------------------------------------------------
__global__ __launch_bounds__(256) void k2_highres(const float* __restrict__ ctx,
                                                  float* __restrict__ out) {
    int idx = blockIdx.x * 256 + threadIdx.x;     // 65536 threads
    int b = idx >> 13;
    int rem = idx & 8191;
    int hr = rem >> 6;          // high-res row 0..127
    int x = rem & 63;           // low-res col -> high-res cols 2x, 2x+1
    int y = hr >> 1;            // low-res row

    const float*  qt  = g_Qt + ((b * C_) * h_ + y) * w_ + x;
    const float2* cp2 = (const float2*)(ctx + (size_t)b * N_ * C_ * (H_ * W_)
                                        + hr * W_) + x;   // stride 8192 float2 per (n,c)

    float2 l0 = make_float2(0.f, 0.f), l1 = l0, l2 = l0;
#pragma unroll 4
    for (int c = 0; c < C_; c++) {
        float q = qt[c * 4096];
        float2 a = cp2[c * 8192];
        float2 d = cp2[(64 + c) * 8192];
        float2 e = cp2[(128 + c) * 8192];
        l0.x = fmaf(a.x, q, l0.x); l0.y = fmaf(a.y, q, l0.y);
        l1.x = fmaf(d.x, q, l1.x); l1.y = fmaf(d.y, q, l1.y);
        l2.x = fmaf(e.x, q, l2.x); l2.y = fmaf(e.y, q, l2.y);
    }
    float l3 = g_Lm[(b * h_ + y) * w_ + x];

    float2 w0, w1, w2, w3;
    {
        float mx = fmaxf(fmaxf(l0.x, l1.x), fmaxf(l2.x, l3));
        float e0 = __expf(l0.x - mx), e1 = __expf(l1.x - mx);
        float e2 = __expf(l2.x - mx), e3 = __expf(l3 - mx);
        float inv = 1.f / (e0 + e1 + e2 + e3);
        w0.x = e0 * inv; w1.x = e1 * inv; w2.x = e2 * inv; w3.x = e3 * inv;
    }
    {
        float mx = fmaxf(fmaxf(l0.y, l1.y), fmaxf(l2.y, l3));
        float e0 = __expf(l0.y - mx), e1 = __expf(l1.y - mx);
        float e2 = __expf(l2.y - mx), e3 = __expf(l3 - mx);
        float inv = 1.f / (e0 + e1 + e2 + e3);
        w0.y = e0 * inv; w1.y = e1 * inv; w2.y = e2 * inv; w3.y = e3 * inv;
    }

    const float* vp = g_Val + ((b * C_) * h_ + y) * w_ + x;
    float2* op = (float2*)(out + (size_t)b * C_ * (H_ * W_) + hr * W_) + x;
#pragma unroll 4
    for (int c = 0; c < C_; c++) {
        float v = vp[c * 4096];
        float2 a = cp2[c * 8192];
        float2 d = cp2[(64 + c) * 8192];
        float2 e = cp2[(128 + c) * 8192];
        float2 o;
        o.x = w3.x * v; o.y = w3.y * v;
        o.x = fmaf(w0.x, a.x, o.x); o.y = fmaf(w0.y, a.y, o.y);
        o.x = fmaf(w1.x, d.x, o.x); o.y = fmaf(w1.y, d.y, o.y);
        o.x = fmaf(w2.x, e.x, o.x); o.y = fmaf(w2.y, e.y, o.y);
        op[c * 8192] = o;
    }
}

// ---------------------------------------------------------------------------
extern "C" void kernel_launch(void* const* d_in, const int* in_sizes, int n_in,
                              void* d_out, int out_size) {
    (void)in_sizes; (void)n_in; (void)out_size;
    const float* contexts = (const float*)d_in[0];
    const float* mainstream = (const float*)d_in[1];
    const float* Wc = (const float*)d_in[2];
    // d_in[3] = bc : cancels in softmax, unused
    const float* Wf = (const float*)d_in[4];
    const float* bf = (const float*)d_in[5];
    const float* Wk = (const float*)d_in[6];
    const float* bk = (const float*)d_in[7];
    const float* Vw = (const float*)d_in[8];
    const float* Vb = (const float*)d_in[9];
    float* out = (float*)d_out;

    k0_precompute<<<32, 256>>>(Wc, Wf, bf);
    dim3 g1(8, 4, 8);  // 8-col tiles, 16-row tiles, batch
    k1_lowres<<<g1, 512>>>(mainstream, Wk, bk, Vw, Vb);
    k2_highres<<<256, 256>>>(contexts, out);
}

// round 4
// speedup vs baseline: 1.1153x; 1.0062x over previous
#include <cuda_runtime.h>
#include <math.h>

#define B_ 8
#define N_ 3
#define C_ 64
#define F_ 128
#define H_ 128
#define W_ 128
#define h_ 64
#define w_ 64

typedef unsigned long long u64t;

// Scratch (device globals -- no allocation allowed)
__device__ float g_A[C_ * F_];              // Wc^T * Wf  [c][f]
__device__ float g_tvec[C_];                // Wc^T * bf
__device__ float g_Qt[B_ * C_ * h_ * w_];   // qt at low res
__device__ float g_Val[B_ * C_ * h_ * w_];  // values at low res
__device__ float g_Lm[B_ * h_ * w_];        // mainstream-key logit

// ---- packed f32x2 helpers ----
__device__ __forceinline__ u64t pk2(float lo, float hi) {
    u64t r; asm("mov.b64 %0, {%1, %2};" : "=l"(r) : "f"(lo), "f"(hi)); return r;
}
__device__ __forceinline__ u64t bc2(float v) { return pk2(v, v); }
__device__ __forceinline__ void unpk(u64t p, float& lo, float& hi) {
    asm("mov.b64 {%0, %1}, %2;" : "=f"(lo), "=f"(hi) : "l"(p));
}
__device__ __forceinline__ void fma2(u64t& d, u64t a, u64t b) {
    asm("fma.rn.f32x2 %0, %1, %2, %0;" : "+l"(d) : "l"(a), "l"(b));
}
__device__ __forceinline__ u64t add2(u64t a, u64t b) {
    u64t r; asm("add.rn.f32x2 %0, %1, %2;" : "=l"(r) : "l"(a), "l"(b)); return r;
}
__device__ __forceinline__ u64t mul2(u64t a, u64t b) {
    u64t r; asm("mul.rn.f32x2 %0, %1, %2;" : "=l"(r) : "l"(a), "l"(b)); return r;
}

// ---------------------------------------------------------------------------
// Kernel 0: A = Wc^T Wf, tvec = Wc^T bf
// ---------------------------------------------------------------------------
__global__ __launch_bounds__(256) void k0_precompute(const float* __restrict__ Wc,
                                                     const float* __restrict__ Wf,
                                                     const float* __restrict__ bf) {
    int i = blockIdx.x * blockDim.x + threadIdx.x;  // 8192 threads
    int c = i >> 7, f = i & 127;
    float s0 = 0.f, s1 = 0.f, s2 = 0.f, s3 = 0.f;
#pragma unroll
    for (int d = 0; d < 64; d += 4) {
        s0 = fmaf(Wc[d * 64 + c],       Wf[d * 128 + f],       s0);
        s1 = fmaf(Wc[(d + 1) * 64 + c], Wf[(d + 1) * 128 + f], s1);
        s2 = fmaf(Wc[(d + 2) * 64 + c], Wf[(d + 2) * 128 + f], s2);
        s3 = fmaf(Wc[(d + 3) * 64 + c], Wf[(d + 3) * 128 + f], s3);
    }
    g_A[i] = (s0 + s1) + (s2 + s3);
    if (i < 64) {
        float t = 0.f;
        for (int d = 0; d < 64; d++) t += Wc[d * 64 + i] * bf[d];
        g_tvec[i] = t;
    }
}

// ---------------------------------------------------------------------------
// Kernel 1 (f32x2, 512 threads): per low-res pixel
//   qt[c] = sum_f A[c,f] m[f] + tvec[c]
//   key[c]= sum_f Wk[c,f] m[f] + bk[c]   (only for Lm = sum_c key*qt)
//   val[c]= 3x3 conv(m,Vw)[c] + Vb[c]
// Block = 16x8 pixel tile of one batch, 512 threads:
//   c  = tid&63   -> one channel
//   pg = tid>>6   -> output row-pair {2pg, 2pg+1}, packed in f32x2 lanes
// Window staged in SMEM as row-PAIRS (float2) so every stencil operand pair is
// an aligned broadcast LDS.64. Weight scalars broadcast-packed via mov.b64.
// ---------------------------------------------------------------------------
#define SWIN 0        // float2[8 fc][17 pairs][10 cols] = 2720 floats
#define SWA  2720     // [8 fc][64 c] = 512
#define SWK  3232     // 512
#define SWV  3744     // [8 fc][64 c][9] = 4608
#define SRED 8352     // u64[16 warps][8 x] = 256 floats
#define STOT 8608     // 34.4 KB; epilogue stage reuses [64][129]=8256 at 0

__global__ __launch_bounds__(512, 1) void k1_lowres(
    const float* __restrict__ ms,   // [B,128,64,64]
    const float* __restrict__ Wk,   // [64,128]
    const float* __restrict__ bk,   // [64]
    const float* __restrict__ Vw,   // [64,128,3,3]
    const float* __restrict__ Vb)   // [64]
{
    __shared__ __align__(16) float sm[STOT];

    const int tid = threadIdx.x;
    const int b = blockIdx.z;
    const int gx0 = blockIdx.x * 8, gy0 = blockIdx.y * 16;
    const int c = tid & 63, pg = tid >> 6;

    u64t vq[8], vk[8], vv[8];
#pragma unroll
    for (int x = 0; x < 8; x++) { vq[x] = vk[x] = vv[x] = 0ull; }

    for (int chunk = 0; chunk < 16; chunk++) {
        const int f0 = chunk * 8;
        __syncthreads();
        // ---- stage window row-pairs (zero-padded SAME halo) ----
        for (int i = tid; i < 1360; i += 512) {
            int fc = i / 170;
            int rem = i - fc * 170;
            int j = rem / 10, col = rem - j * 10;
            int gy = gy0 + j - 1, gx = gx0 + col - 1;
            float lo = 0.f, hi = 0.f;
            if (gx >= 0 && gx < w_) {
                const float* base = ms + ((size_t)(b * F_ + f0 + fc) * h_) * w_ + gx;
                if (gy >= 0 && gy < h_) lo = base[gy * w_];
                if (gy + 1 < h_) hi = base[(gy + 1) * w_];
            }
            ((float2*)sm)[i] = make_float2(lo, hi);
        }
        // ---- stage weights ----
        {
            int cc = tid >> 3, fc = tid & 7;
            sm[SWA + fc * 64 + cc] = g_A[cc * F_ + f0 + fc];
            sm[SWK + fc * 64 + cc] = Wk[cc * F_ + f0 + fc];
        }
        for (int i = tid; i < 4608; i += 512) {
            int cc = i / 72;
            int r = i - cc * 72;
            int fc = r / 9, j = r - fc * 9;
            sm[SWV + (fc * 64 + cc) * 9 + j] = Vw[(cc * F_ + f0 + fc) * 9 + j];
        }
        __syncthreads();

#pragma unroll 1
        for (int fc = 0; fc < 8; fc++) {
            u64t wap = bc2(sm[SWA + fc * 64 + c]);
            u64t wkp = bc2(sm[SWK + fc * 64 + c]);
            u64t vwp[9];
#pragma unroll
            for (int j = 0; j < 9; j++)
                vwp[j] = bc2(sm[SWV + (fc * 64 + c) * 9 + j]);
            const u64t* win = (const u64t*)sm + (fc * 17 + 2 * pg) * 10;
#pragma unroll
            for (int u = 0; u < 3; u++) {
                u64t w[10];
#pragma unroll
                for (int t = 0; t < 10; t++) w[t] = win[u * 10 + t];
#pragma unroll
                for (int x = 0; x < 8; x++) {
                    fma2(vv[x], vwp[3 * u + 0], w[x]);
                    fma2(vv[x], vwp[3 * u + 1], w[x + 1]);
                    fma2(vv[x], vwp[3 * u + 2], w[x + 2]);
                }
                if (u == 1) {
#pragma unroll
                    for (int x = 0; x < 8; x++) {
                        fma2(vq[x], wap, w[x + 1]);
                        fma2(vk[x], wkp, w[x + 1]);
                    }
                }
            }
        }
    }

    // ---- epilogue ----
    u64t tqp = bc2(g_tvec[c]);
    u64t kbp = bc2(bk[c]);
    u64t vbp = bc2(Vb[c]);

    u64t qf[8], lm[8];
#pragma unroll
    for (int x = 0; x < 8; x++) {
        qf[x] = add2(vq[x], tqp);
        lm[x] = mul2(add2(vk[x], kbp), qf[x]);
    }
    // warp shuffle-reduce over 32 channels (warp has fixed pg)
#pragma unroll
    for (int off = 16; off; off >>= 1) {
#pragma unroll
        for (int x = 0; x < 8; x++)
            lm[x] = add2(lm[x], __shfl_down_sync(0xffffffffu, lm[x], off));
    }
    __syncthreads();  // compute done; smem reusable
    const int warp = tid >> 5;
    if ((tid & 31) == 0) {
        u64t* red = (u64t*)sm + SRED / 2;
#pragma unroll
        for (int x = 0; x < 8; x++) red[warp * 8 + x] = lm[x];
    }
    // stage q transposed to [c][16 rows][8 cols] (pitch 129 kills conflicts)
#pragma unroll
    for (int x = 0; x < 8; x++) {
        float lo, hi; unpk(qf[x], lo, hi);
        sm[c * 129 + (2 * pg) * 8 + x] = lo;
        sm[c * 129 + (2 * pg + 1) * 8 + x] = hi;
    }
    __syncthreads();
    if (tid < 64) {  // combine the two warps per pg, write Lm
        int pg2 = tid >> 3, x = tid & 7;
        const u64t* red = (const u64t*)sm + SRED / 2;
        u64t L = add2(red[(2 * pg2) * 8 + x], red[(2 * pg2 + 1) * 8 + x]);
        float lo, hi; unpk(L, lo, hi);
        g_Lm[(b * h_ + gy0 + 2 * pg2) * w_ + gx0 + x] = lo;
        g_Lm[(b * h_ + gy0 + 2 * pg2 + 1) * w_ + gx0 + x] = hi;
    }
#pragma unroll
    for (int j = 0; j < 16; j++) {
        int i = j * 512 + tid;
        int cc = i >> 7, p = i & 127;
        g_Qt[((b * C_ + cc) * h_ + gy0 + (p >> 3)) * w_ + gx0 + (p & 7)] =
            sm[cc * 129 + p];
    }
    __syncthreads();
#pragma unroll
    for (int x = 0; x < 8; x++) {
        float lo, hi; unpk(add2(vv[x], vbp), lo, hi);
        sm[c * 129 + (2 * pg) * 8 + x] = lo;
        sm[c * 129 + (2 * pg + 1) * 8 + x] = hi;
    }
    __syncthreads();
#pragma unroll
    for (int j = 0; j < 16; j++) {
        int i = j * 512 + tid;
        int cc = i >> 7, p = i & 127;
        g_Val[((b * C_ + cc) * h_ + gy0 + (p >> 3)) * w_ + gx0 + (p & 7)] =
            sm[cc * 129 + p];
    }
}

// ---------------------------------------------------------------------------
// Kernel 2: high-res attention. One thread per 2 adjacent output pixels
// (same low-res source pixel) -> float2 ctx loads, amortized qt/Lm/Val.
// ---------------------------------------------------------------------------
__global__ __launch_bounds__(256) void k2_highres(const float* __restrict__ ctx,
                                                  float* __restrict__ out) {
    int idx = blockIdx.x * 256 + threadIdx.x;     // 65536 threads
    int b = idx >> 13;
    int rem = idx & 8191;
    int hr = rem >> 6;          // high-res row 0..127
    int x = rem & 63;           // low-res col -> high-res cols 2x, 2x+1
    int y = hr >> 1;            // low-res row

    const float*  qt  = g_Qt + ((b * C_) * h_ + y) * w_ + x;
    const float2* cp2 = (const float2*)(ctx + (size_t)b * N_ * C_ * (H_ * W_)
                                        + hr * W_) + x;   // stride 8192 float2 per (n,c)

    float2 l0 = make_float2(0.f, 0.f), l1 = l0, l2 = l0;
#pragma unroll 4
    for (int c = 0; c < C_; c++) {
        float q = qt[c * 4096];
        float2 a = cp2[c * 8192];
        float2 d = cp2[(64 + c) * 8192];
        float2 e = cp2[(128 + c) * 8192];
        l0.x = fmaf(a.x, q, l0.x); l0.y = fmaf(a.y, q, l0.y);
        l1.x = fmaf(d.x, q, l1.x); l1.y = fmaf(d.y, q, l1.y);
        l2.x = fmaf(e.x, q, l2.x); l2.y = fmaf(e.y, q, l2.y);
    }
    float l3 = g_Lm[(b * h_ + y) * w_ + x];

    float2 w0, w1, w2, w3;
    {
        float mx = fmaxf(fmaxf(l0.x, l1.x), fmaxf(l2.x, l3));
        float e0 = __expf(l0.x - mx), e1 = __expf(l1.x - mx);
        float e2 = __expf(l2.x - mx), e3 = __expf(l3 - mx);
        float inv = 1.f / (e0 + e1 + e2 + e3);
        w0.x = e0 * inv; w1.x = e1 * inv; w2.x = e2 * inv; w3.x = e3 * inv;
    }
    {
        float mx = fmaxf(fmaxf(l0.y, l1.y), fmaxf(l2.y, l3));
        float e0 = __expf(l0.y - mx), e1 = __expf(l1.y - mx);
        float e2 = __expf(l2.y - mx), e3 = __expf(l3 - mx);
        float inv = 1.f / (e0 + e1 + e2 + e3);
        w0.y = e0 * inv; w1.y = e1 * inv; w2.y = e2 * inv; w3.y = e3 * inv;
    }

    const float* vp = g_Val + ((b * C_) * h_ + y) * w_ + x;
    float2* op = (float2*)(out + (size_t)b * C_ * (H_ * W_) + hr * W_) + x;
#pragma unroll 4
    for (int c = 0; c < C_; c++) {
        float v = vp[c * 4096];
        float2 a = cp2[c * 8192];
        float2 d = cp2[(64 + c) * 8192];
        float2 e = cp2[(128 + c) * 8192];
        float2 o;
        o.x = w3.x * v; o.y = w3.y * v;
        o.x = fmaf(w0.x, a.x, o.x); o.y = fmaf(w0.y, a.y, o.y);
        o.x = fmaf(w1.x, d.x, o.x); o.y = fmaf(w1.y, d.y, o.y);
        o.x = fmaf(w2.x, e.x, o.x); o.y = fmaf(w2.y, e.y, o.y);
        op[c * 8192] = o;
    }
}

// ---------------------------------------------------------------------------
extern "C" void kernel_launch(void* const* d_in, const int* in_sizes, int n_in,
                              void* d_out, int out_size) {
    (void)in_sizes; (void)n_in; (void)out_size;
    const float* contexts = (const float*)d_in[0];
    const float* mainstream = (const float*)d_in[1];
    const float* Wc = (const float*)d_in[2];
    // d_in[3] = bc : cancels in softmax, unused
    const float* Wf = (const float*)d_in[4];
    const float* bf = (const float*)d_in[5];
    const float* Wk = (const float*)d_in[6];
    const float* bk = (const float*)d_in[7];
    const float* Vw = (const float*)d_in[8];
    const float* Vb = (const float*)d_in[9];
    float* out = (float*)d_out;

    k0_precompute<<<32, 256>>>(Wc, Wf, bf);
    dim3 g1(8, 4, 8);  // 8-col tiles, 16-row tiles, batch
    k1_lowres<<<g1, 512>>>(mainstream, Wk, bk, Vw, Vb);
    k2_highres<<<256, 256>>>(contexts, out);
}